// round 9
// baseline (speedup 1.0000x reference)
#include <cuda_runtime.h>

#define NCH  8
#define NXI  128
#define NYI  128
#define KTOT 16384

__device__ __forceinline__ float gldg(const float* p, int i, int n) {
    return (i < n) ? __ldg(p + i) : 0.0f;
}

// ---------------------------------------------------------------------------
// Register-only NUFFT. Thread -> one k-sample, two channels {c0, c0+1}.
//   out(c,k) = sum_x px(k,x) * ( sum_y img[c,x,y] * py(k,y) )
// Output layout adaptive on reported capacity:
//   planar_real (n_out < 262144): out[c*K + k] = Re(ksp)   (131072 floats)
//   interleaved (n_out >= 262144): out[2*(c*K+k)] = Re, +1 = Im
// Every store guarded by n_out (floats).
// ---------------------------------------------------------------------------
__global__ void __launch_bounds__(128)
nufft_v9(const float* __restrict__ re, int n_re,
         const float* __restrict__ im, int n_im,
         const float* __restrict__ trj, int n_trj,
         float* __restrict__ out, int n_out, int interleaved) {
    int gid = blockIdx.x * 128 + threadIdx.x;   // 0 .. 65535
    int k   = gid & (KTOT - 1);                 // 0 .. 16383
    int cg  = gid >> 14;                        // 0 .. 3
    int c0  = 2 * cg;

    float tx = gldg(trj, 2 * k,     n_trj);
    float ty = gldg(trj, 2 * k + 1, n_trj);

    // x=0 (xc=-64): px = exp(+i*pi*tx); step exp(-i*pi*tx/64). Same for y.
    float pxr, pxi, wxr, wxi;
    sincospif(tx, &pxi, &pxr);
    sincospif(-tx * (1.0f / 64.0f), &wxi, &wxr);
    float py0r, py0i, wyr, wyi;
    sincospif(ty, &py0i, &py0r);
    sincospif(-ty * (1.0f / 64.0f), &wyi, &wyr);

    const int chan = NXI * NYI;
    const float* re0 = re + c0 * chan;
    const float* im0 = im + c0 * chan;

    float ar0 = 0.0f, ai0 = 0.0f, ar1 = 0.0f, ai1 = 0.0f;

    bool fast = ((c0 + 2) * chan <= n_re) && ((c0 + 2) * chan <= n_im);

    if (fast) {
        for (int x = 0; x < NXI; x++) {
            float pyr = py0r, pyi = py0i;
            float sr0 = 0, si0 = 0, sr1 = 0, si1 = 0;
            int base = x * NYI;
#pragma unroll 4
            for (int y = 0; y < NYI; y += 4) {
                float4 r0 = *(const float4*)(re0 + base + y);
                float4 i0 = *(const float4*)(im0 + base + y);
                float4 r1 = *(const float4*)(re0 + chan + base + y);
                float4 i1 = *(const float4*)(im0 + chan + base + y);

                sr0 += r0.x * pyr - i0.x * pyi; si0 += r0.x * pyi + i0.x * pyr;
                sr1 += r1.x * pyr - i1.x * pyi; si1 += r1.x * pyi + i1.x * pyr;
                { float t = pyr * wyr - pyi * wyi;
                  pyi = pyr * wyi + pyi * wyr; pyr = t; }

                sr0 += r0.y * pyr - i0.y * pyi; si0 += r0.y * pyi + i0.y * pyr;
                sr1 += r1.y * pyr - i1.y * pyi; si1 += r1.y * pyi + i1.y * pyr;
                { float t = pyr * wyr - pyi * wyi;
                  pyi = pyr * wyi + pyi * wyr; pyr = t; }

                sr0 += r0.z * pyr - i0.z * pyi; si0 += r0.z * pyi + i0.z * pyr;
                sr1 += r1.z * pyr - i1.z * pyi; si1 += r1.z * pyi + i1.z * pyr;
                { float t = pyr * wyr - pyi * wyi;
                  pyi = pyr * wyi + pyi * wyr; pyr = t; }

                sr0 += r0.w * pyr - i0.w * pyi; si0 += r0.w * pyi + i0.w * pyr;
                sr1 += r1.w * pyr - i1.w * pyi; si1 += r1.w * pyi + i1.w * pyr;
                { float t = pyr * wyr - pyi * wyi;
                  pyi = pyr * wyi + pyi * wyr; pyr = t; }
            }
            ar0 += sr0 * pxr - si0 * pxi;  ai0 += sr0 * pxi + si0 * pxr;
            ar1 += sr1 * pxr - si1 * pxi;  ai1 += sr1 * pxi + si1 * pxr;
            { float t = pxr * wxr - pxi * wxi;
              pxi = pxr * wxi + pxi * wxr; pxr = t; }
        }
    } else {
        for (int x = 0; x < NXI; x++) {
            float pyr = py0r, pyi = py0i;
            float sr0 = 0, si0 = 0, sr1 = 0, si1 = 0;
            int base = c0 * chan + x * NYI;
            for (int y = 0; y < NYI; y++) {
                float br0 = gldg(re, base + y,        n_re);
                float bi0 = gldg(im, base + y,        n_im);
                float br1 = gldg(re, base + chan + y, n_re);
                float bi1 = gldg(im, base + chan + y, n_im);
                sr0 += br0 * pyr - bi0 * pyi; si0 += br0 * pyi + bi0 * pyr;
                sr1 += br1 * pyr - bi1 * pyi; si1 += br1 * pyi + bi1 * pyr;
                float t = pyr * wyr - pyi * wyi;
                pyi = pyr * wyi + pyi * wyr; pyr = t;
            }
            ar0 += sr0 * pxr - si0 * pxi;  ai0 += sr0 * pxi + si0 * pxr;
            ar1 += sr1 * pxr - si1 * pxi;  ai1 += sr1 * pxi + si1 * pxr;
            float t = pxr * wxr - pxi * wxi;
            pxi = pxr * wxi + pxi * wxr; pxr = t;
        }
    }

    if (interleaved) {
        int o0 = 2 * (c0 * KTOT + k);
        int o1 = 2 * ((c0 + 1) * KTOT + k);
        if (o0 + 1 < n_out) { out[o0] = ar0; out[o0 + 1] = ai0; }
        if (o1 + 1 < n_out) { out[o1] = ar1; out[o1 + 1] = ai1; }
    } else {
        // planar real-only: out[c*K + k] = Re(ksp[c][k])
        int o0 = c0 * KTOT + k;
        int o1 = (c0 + 1) * KTOT + k;
        if (o0 < n_out) out[o0] = ar0;
        if (o1 < n_out) out[o1] = ar1;
    }
}

// ---------------------------------------------------------------------------
extern "C" void kernel_launch(void* const* d_in, const int* in_sizes, int n_in,
                              void* d_out, int out_size) {
    // Documented metadata (setup_inputs dict) order:
    //   d_in[0]=img_real, d_in[1]=img_imag, d_in[2]=trj.
    const float* img_real = (const float*)d_in[0];
    const float* img_imag = (const float*)d_in[1];
    const float* trj      = (const float*)d_in[2];

    int n_re  = in_sizes[0] < NCH * NXI * NYI ? in_sizes[0] : NCH * NXI * NYI;
    int n_im  = in_sizes[1] < NCH * NXI * NYI ? in_sizes[1] : NCH * NXI * NYI;
    int n_trj = in_sizes[2] < 2 * KTOT        ? in_sizes[2] : 2 * KTOT;

    // Evidence (R1-R8): buffer capacity == out_size * 4 bytes. If out_size
    // can hold the full interleaved complex result (262144 floats), write it;
    // otherwise the output dtype is float32 (8,16384) -> real part only.
    int n_out = out_size < 2 * NCH * KTOT ? out_size : 2 * NCH * KTOT;
    int interleaved = (out_size >= 2 * NCH * KTOT) ? 1 : 0;

    nufft_v9<<<512, 128>>>(img_real, n_re, img_imag, n_im,
                           trj, n_trj, (float*)d_out, n_out, interleaved);
}

// round 10
// speedup vs baseline: 1.6489x; 1.6489x over previous
#include <cuda_runtime.h>

#define NCH  8
#define NXI  128
#define NYI  128
#define KTOT 16384
#define KT   128
#define NTH  256

// Pre-transposed image: [c][y][xq] where each float4 = complex pair
// (re(x), im(x), re(x+1), im(x+1)) for x = 2*xq. 8192 float4 = 128 KB.
__device__ float4 g_img4[NCH * NYI * (NXI / 2)];

// ---------------------------------------------------------------------------
// Transpose (c,x,y) split re/im -> (c,y,x) interleaved pairs. Runs once.
// ---------------------------------------------------------------------------
__global__ void transpose_k(const float* __restrict__ re, int n_re,
                            const float* __restrict__ im, int n_im) {
    int idx = blockIdx.x * 256 + threadIdx.x;    // 0..8191 float4 index
    int xq = idx & 63;
    int y  = (idx >> 6) & 127;
    int c  = idx >> 13;
    int s0 = c * 16384 + (2 * xq) * 128 + y;     // img[c, 2xq,   y]
    int s1 = s0 + 128;                           // img[c, 2xq+1, y]
    float r0 = (s0 < n_re) ? re[s0] : 0.0f;
    float i0 = (s0 < n_im) ? im[s0] : 0.0f;
    float r1 = (s1 < n_re) ? re[s1] : 0.0f;
    float i1 = (s1 < n_im) ? im[s1] : 0.0f;
    g_img4[idx] = make_float4(r0, i0, r1, i1);
}

// ---------------------------------------------------------------------------
// Packed f32x2 FMA + unpack
// ---------------------------------------------------------------------------
__device__ __forceinline__ unsigned long long ffma2(unsigned long long a,
                                                    unsigned long long b,
                                                    unsigned long long c) {
    unsigned long long d;
    asm("fma.rn.f32x2 %0, %1, %2, %3;" : "=l"(d) : "l"(a), "l"(b), "l"(c));
    return d;
}
__device__ __forceinline__ float2 uf2(unsigned long long v) {
    float2 f;
    asm("mov.b64 {%0,%1}, %2;" : "=f"(f.x), "=f"(f.y) : "l"(v));
    return f;
}

// ---------------------------------------------------------------------------
// Main kernel. Block: KT=128 k x 8 channels. Thread: 4 k x 1 c.
//   smem: px[x][k] 128 KB + dup img slices 2 x 16.5 KB + trj 1 KB
// ---------------------------------------------------------------------------
#define PX_BYTES        (NXI * KT * 8)          // 131072
#define IMG_STRIDE      129                     // float4 per c-row (padded)
#define IMG_SLICE_F4    (NCH * IMG_STRIDE)      // 1032
#define IMG_SLICE_BYTES (IMG_SLICE_F4 * 16)     // 16512
#define SMEM_TOTAL      (PX_BYTES + 2 * IMG_SLICE_BYTES + 1024)

__global__ void __launch_bounds__(NTH, 1)
nufft_f32x2(const float* __restrict__ trj, int n_trj,
            float* __restrict__ out, int n_out, int interleaved) {
    extern __shared__ char smem[];
    float2*           pxf   = (float2*)smem;               // write [x*128+k]
    const ulonglong2* pxq   = (const ulonglong2*)smem;     // read  (2 cplx)
    float4*           imgw  = (float4*)(smem + PX_BYTES);
    const ulonglong2* imgr  = (const ulonglong2*)(smem + PX_BYTES);
    float*            trj_s = (float*)(smem + PX_BYTES + 2 * IMG_SLICE_BYTES);

    int tid   = threadIdx.x;
    int kbase = blockIdx.x * KT;

    int t_idx = kbase * 2 + tid;                // 256 floats of trj tile
    trj_s[tid] = (t_idx < n_trj) ? __ldg(&trj[t_idx]) : 0.0f;
    __syncthreads();

    // px[x][k] = exp(-i*pi*tx_k*(x-64)/64)
#pragma unroll 4
    for (int i = 0; i < 64; i++) {
        int idx = tid + (i << 8);
        int x = idx >> 7, k = idx & 127;
        float t = trj_s[2 * k];
        float a = t * (float)(x - 64) * (-1.0f / 64.0f);
        float s, c;
        sincospif(a, &s, &c);
        pxf[idx] = make_float2(c, s);
    }

    int kq = tid >> 3;     // 0..31 : k quad {4kq..4kq+3}
    int ch = tid & 7;      // 0..7

    // py recurrence: start exp(+i*pi*ty) (y=0 -> yc=-64), step exp(-i*pi*ty/64)
    float cyr[4], cyi[4], wyr[4], wyi[4];
#pragma unroll
    for (int j = 0; j < 4; j++) {
        float ty = trj_s[2 * (4 * kq + j) + 1];
        sincospif(ty, &cyi[j], &cyr[j]);
        sincospif(-ty * (1.0f / 64.0f), &wyi[j], &wyr[j]);
    }

    float accr[4] = {0, 0, 0, 0}, acci[4] = {0, 0, 0, 0};

    // prefetch slice y=0: 512 float4 / 256 threads = 2 each (coalesced)
    float4 r[2];
#pragma unroll
    for (int i = 0; i < 2; i++) {
        int e = tid + (i << 8);                 // e = c*64 + xq
        r[i] = g_img4[(e >> 6) * 8192 + (e & 63)];
    }

    for (int y = 0; y < 128; y++) {
        int buf = y & 1;
        float4* dst = imgw + buf * IMG_SLICE_F4;
        // stage slice in duplicated form (br,br,bi,bi)
#pragma unroll
        for (int i = 0; i < 2; i++) {
            int e = tid + (i << 8);
            int c = e >> 6, xq = e & 63;
            dst[c * IMG_STRIDE + 2 * xq]     = make_float4(r[i].x, r[i].x,
                                                           r[i].y, r[i].y);
            dst[c * IMG_STRIDE + 2 * xq + 1] = make_float4(r[i].z, r[i].z,
                                                           r[i].w, r[i].w);
        }
        if (y < 127) {
#pragma unroll
            for (int i = 0; i < 2; i++) {
                int e = tid + (i << 8);
                r[i] = g_img4[(e >> 6) * 8192 + (y + 1) * 64 + (e & 63)];
            }
        }
        __syncthreads();

        unsigned long long P0 = 0, P1 = 0, P2 = 0, P3 = 0;
        unsigned long long Q0 = 0, Q1 = 0, Q2 = 0, Q3 = 0;
        const ulonglong2* p  = pxq + kq * 2;    // 32 bytes per kq
        const ulonglong2* ib = imgr + buf * IMG_SLICE_F4 + ch * IMG_STRIDE;
#pragma unroll 16
        for (int x = 0; x < 128; x++) {
            ulonglong2 A = p[0];      // k = 4kq, 4kq+1  (ar,ai | ar,ai)
            ulonglong2 B = p[1];      // k = 4kq+2, 4kq+3
            ulonglong2 I = ib[0];     // .x = (br,br)  .y = (bi,bi)
            P0 = ffma2(I.x, A.x, P0);  Q0 = ffma2(I.y, A.x, Q0);
            P1 = ffma2(I.x, A.y, P1);  Q1 = ffma2(I.y, A.y, Q1);
            P2 = ffma2(I.x, B.x, P2);  Q2 = ffma2(I.y, B.x, Q2);
            P3 = ffma2(I.x, B.y, P3);  Q3 = ffma2(I.y, B.y, Q3);
            p  += 64;   // next x row (64 ulonglong2 = 128 float2)
            ib += 1;
        }

        unsigned long long Ps[4] = {P0, P1, P2, P3};
        unsigned long long Qs[4] = {Q0, Q1, Q2, Q3};
#pragma unroll
        for (int j = 0; j < 4; j++) {
            float2 Pf = uf2(Ps[j]);   // (sum ar*br, sum ar*bi)
            float2 Qf = uf2(Qs[j]);   // (sum ai*br, sum ai*bi)
            float trr = Pf.x - Qf.y;
            float tii = Pf.y + Qf.x;
            accr[j] += trr * cyr[j] - tii * cyi[j];
            acci[j] += trr * cyi[j] + tii * cyr[j];
            float nr = cyr[j] * wyr[j] - cyi[j] * wyi[j];
            float ni = cyr[j] * wyi[j] + cyi[j] * wyr[j];
            cyr[j] = nr; cyi[j] = ni;
        }
    }

    // output: adaptive layout, every store guarded (proven in R9)
#pragma unroll
    for (int j = 0; j < 4; j++) {
        int k = kbase + 4 * kq + j;
        if (interleaved) {
            int o = 2 * (ch * KTOT + k);
            if (o + 1 < n_out) { out[o] = accr[j]; out[o + 1] = acci[j]; }
        } else {
            int o = ch * KTOT + k;
            if (o < n_out) out[o] = accr[j];
        }
    }
}

// ---------------------------------------------------------------------------
extern "C" void kernel_launch(void* const* d_in, const int* in_sizes, int n_in,
                              void* d_out, int out_size) {
    // Documented order: d_in[0]=img_real, d_in[1]=img_imag, d_in[2]=trj.
    const float* img_real = (const float*)d_in[0];
    const float* img_imag = (const float*)d_in[1];
    const float* trj      = (const float*)d_in[2];

    int n_re  = in_sizes[0] < NCH * NXI * NYI ? in_sizes[0] : NCH * NXI * NYI;
    int n_im  = in_sizes[1] < NCH * NXI * NYI ? in_sizes[1] : NCH * NXI * NYI;
    int n_trj = in_sizes[2] < 2 * KTOT        ? in_sizes[2] : 2 * KTOT;

    int n_out = out_size < 2 * NCH * KTOT ? out_size : 2 * NCH * KTOT;
    int interleaved = (out_size >= 2 * NCH * KTOT) ? 1 : 0;

    cudaFuncSetAttribute(nufft_f32x2,
                         cudaFuncAttributeMaxDynamicSharedMemorySize,
                         SMEM_TOTAL);

    transpose_k<<<(NCH * NYI * (NXI / 2)) / 256, 256>>>(img_real, n_re,
                                                        img_imag, n_im);
    nufft_f32x2<<<KTOT / KT, NTH, SMEM_TOTAL>>>(trj, n_trj,
                                                (float*)d_out, n_out,
                                                interleaved);
}